// round 10
// baseline (speedup 1.0000x reference)
#include <cuda_runtime.h>

#define N_RES 2048
#define BATCH 16
#define LMAXP 13
#define NTYPES 20
#define MAXROWS 28672
#define MAXATOMS 26624
#define ROWS_PER_BLK 8

#define WATM_T_ELEMS (NTYPES * LMAXP * LMAXP * 64)   // 216320
#define WAMN_T_ELEMS (NTYPES * LMAXP * 64)           // 16640

__constant__ int c_reslen[NTYPES] = {3, 4, 5, 5, 6, 6, 6, 7, 7, 7, 7, 7, 8, 8, 8, 9, 10, 10, 11, 13};

__device__ int g_starts[N_RES];
// Per-row descriptor: {type, m (-1 for amn row), residue, start}
__device__ int4 g_rowdesc[MAXROWS];
// Pre-transposed weights: WatmT[t][m][l][v], WamnT[t][l][o]
__device__ float g_WatmT[WATM_T_ELEMS];
__device__ float g_WamnT[WAMN_T_ELEMS];
// Precomputed diffs, padded to float4: g_diff[b*atoms + a] = pos_atm - pos_amn
__device__ float4 g_diff[BATCH * MAXATOMS];

// ---------------------------------------------------------------------------
// Kernel A: exclusive prefix-sum of residue lengths -> g_starts (1 block).
// ---------------------------------------------------------------------------
__global__ void scan_kernel(const int* __restrict__ seq) {
    int t = threadIdx.x;  // 0..1023
    int l0 = c_reslen[seq[2 * t]];
    int l1 = c_reslen[seq[2 * t + 1]];
    int a = l0 + l1;

    int v = a;
#pragma unroll
    for (int off = 1; off < 32; off <<= 1) {
        int n = __shfl_up_sync(0xFFFFFFFFu, v, off);
        if ((t & 31) >= off) v += n;
    }

    __shared__ int wsum[32];
    if ((t & 31) == 31) wsum[t >> 5] = v;
    __syncthreads();
    if (t < 32) {
        int s = wsum[t];
        int x = s;
#pragma unroll
        for (int off = 1; off < 32; off <<= 1) {
            int n = __shfl_up_sync(0xFFFFFFFFu, x, off);
            if (t >= off) x += n;
        }
        wsum[t] = x - s;
    }
    __syncthreads();

    int excl = wsum[t >> 5] + (v - a);
    g_starts[2 * t] = excl;
    g_starts[2 * t + 1] = excl + l0;
}

// ---------------------------------------------------------------------------
// Kernel B: parallel row-descriptor fill. One thread per residue.
// ---------------------------------------------------------------------------
__global__ void fill_kernel(const int* __restrict__ seq, int atoms) {
    int i = blockIdx.x * blockDim.x + threadIdx.x;
    if (i >= N_RES) return;
    int t = seq[i];
    int L = c_reslen[t];
    int start = g_starts[i];
    for (int l = 0; l < L; l++) g_rowdesc[start + l] = make_int4(t, l, i, start);
    g_rowdesc[atoms + i] = make_int4(t, -1, i, start);
}

// ---------------------------------------------------------------------------
// Kernel C: transpose weights for coalesced per-lane access.
//   g_WatmT[((t*13+m)*13+l)*64 + v] = W_atm[((t*13+m)*64+v)*13 + l]
//   g_WamnT[(t*13+l)*64 + o]        = W_amn[(t*64+o)*13 + l]
// ---------------------------------------------------------------------------
__global__ void transpose_w_kernel(const float* __restrict__ W_amn,
                                   const float* __restrict__ W_atm) {
    int idx = blockIdx.x * blockDim.x + threadIdx.x;
    if (idx < WATM_T_ELEMS) {
        int v = idx & 63;
        int r = idx >> 6;
        int l = r % LMAXP; r /= LMAXP;
        int m = r % LMAXP;
        int t = r / LMAXP;
        g_WatmT[idx] = W_atm[((size_t)(t * LMAXP + m) * 64 + v) * LMAXP + l];
    } else {
        int j = idx - WATM_T_ELEMS;
        if (j < WAMN_T_ELEMS) {
            int o = j & 63;
            int r = j >> 6;
            int l = r % LMAXP;
            int t = r / LMAXP;
            g_WamnT[j] = W_amn[((size_t)t * 64 + o) * LMAXP + l];
        }
    }
}

// ---------------------------------------------------------------------------
// Kernel E: precompute diffs into float4 scratch (L2-resident, 3.9MB).
// One thread per (b, atom).
// ---------------------------------------------------------------------------
__global__ void diff_kernel(const float* __restrict__ pos_atm,
                            const float* __restrict__ pos_amn,
                            int atoms) {
    int idx = blockIdx.x * blockDim.x + threadIdx.x;
    if (idx >= BATCH * atoms) return;
    int b = idx / atoms;
    int a = idx - b * atoms;
    int ri = g_rowdesc[a].z;
    const float* pa = pos_atm + (size_t)idx * 3;
    const float* pm = pos_amn + ((size_t)b * N_RES + ri) * 3;
    g_diff[idx] = make_float4(pa[0] - pm[0], pa[1] - pm[1], pa[2] - pm[2], 0.f);
}

// ---------------------------------------------------------------------------
// Per-row compute: one warp per row, lane owns v = 2*lane, 2*lane+1.
// 6 contiguous output floats per lane -> 3 STG.64; weights via 1 LDG.64 per l.
// ---------------------------------------------------------------------------
template <int L>
__device__ __forceinline__ void row_compute(
    const float4* __restrict__ gd,    // g_diff + start, stride `atoms` per batch
    int atoms,
    const float* __restrict__ wt,     // transposed weight row base + 2*lane
    float* __restrict__ obase,        // + 6*lane applied by caller
    size_t ostride)
{
    float2 wv[L];
#pragma unroll
    for (int l = 0; l < L; l++)
        wv[l] = *reinterpret_cast<const float2*>(wt + l * 64);

    for (int b = 0; b < BATCH; b++) {
        const float4* d = gd + (size_t)b * atoms;
        float x0 = 0.f, y0 = 0.f, z0 = 0.f;
        float x1 = 0.f, y1 = 0.f, z1 = 0.f;
#pragma unroll
        for (int l = 0; l < L; l++) {
            float4 v4 = __ldg(d + l);
            x0 = fmaf(wv[l].x, v4.x, x0);
            y0 = fmaf(wv[l].x, v4.y, y0);
            z0 = fmaf(wv[l].x, v4.z, z0);
            x1 = fmaf(wv[l].y, v4.x, x1);
            y1 = fmaf(wv[l].y, v4.y, y1);
            z1 = fmaf(wv[l].y, v4.z, z1);
        }
        float* o = obase + (size_t)b * ostride;
        reinterpret_cast<float2*>(o)[0] = make_float2(x0, y0);
        reinterpret_cast<float2*>(o)[1] = make_float2(z0, x1);
        reinterpret_cast<float2*>(o)[2] = make_float2(y1, z1);
    }
}

// ---------------------------------------------------------------------------
// Kernel D: main. One warp per output row. No smem, no barriers.
// ---------------------------------------------------------------------------
__global__ void __launch_bounds__(256, 4) posmix_main(
    float* __restrict__ out_atm,
    float* __restrict__ out_amn,
    int atoms, int nrows)
{
    const int tid = threadIdx.x;
    const int warp = tid >> 5;
    const int lane = tid & 31;
    const int row = blockIdx.x * ROWS_PER_BLK + warp;
    if (row >= nrows) return;

    const int4 dsc = g_rowdesc[row];
    const int t = dsc.x;
    const int m = dsc.y;
    const int ri = dsc.z;
    const int start = dsc.w;
    const int L = c_reslen[t];

    const float4* gd = g_diff + start;
    const float* wt;
    float* obase;
    size_t ostride;
    if (m >= 0) {
        wt = g_WatmT + (size_t)((t * LMAXP + m) * LMAXP) * 64 + 2 * lane;
        obase = out_atm + (size_t)row * 192 + 6 * lane;
        ostride = (size_t)atoms * 192;
    } else {
        wt = g_WamnT + (size_t)(t * LMAXP) * 64 + 2 * lane;
        obase = out_amn + (size_t)ri * 192 + 6 * lane;
        ostride = (size_t)N_RES * 192;
    }

    switch (L) {
        case 3:  row_compute<3 >(gd, atoms, wt, obase, ostride); break;
        case 4:  row_compute<4 >(gd, atoms, wt, obase, ostride); break;
        case 5:  row_compute<5 >(gd, atoms, wt, obase, ostride); break;
        case 6:  row_compute<6 >(gd, atoms, wt, obase, ostride); break;
        case 7:  row_compute<7 >(gd, atoms, wt, obase, ostride); break;
        case 8:  row_compute<8 >(gd, atoms, wt, obase, ostride); break;
        case 9:  row_compute<9 >(gd, atoms, wt, obase, ostride); break;
        case 10: row_compute<10>(gd, atoms, wt, obase, ostride); break;
        case 11: row_compute<11>(gd, atoms, wt, obase, ostride); break;
        case 13: row_compute<13>(gd, atoms, wt, obase, ostride); break;
        default: break;
    }
}

// ---------------------------------------------------------------------------
// Launch
// in: 0 pos_atm (B, atoms, 3) f32
//     1 pos_amn (B, 2048, 3) f32
//     2 W_amn   (20, 64, 13) f32
//     3 W_atm   (20, 13, 64, 13) f32
//     4 seq_types (2048,) i32
// out: [x_v_atm (B, atoms, 64, 3) | x_v_amn (B, 2048, 64, 3)] f32
// ---------------------------------------------------------------------------
extern "C" void kernel_launch(void* const* d_in, const int* in_sizes, int n_in,
                              void* d_out, int out_size)
{
    const float* pos_atm = (const float*)d_in[0];
    const float* pos_amn = (const float*)d_in[1];
    const float* W_amn   = (const float*)d_in[2];
    const float* W_atm   = (const float*)d_in[3];
    const int*   seq     = (const int*)d_in[4];

    const int atoms = in_sizes[0] / (BATCH * 3);
    const int nrows = atoms + N_RES;

    float* out_atm = (float*)d_out;
    float* out_amn = out_atm + (size_t)BATCH * atoms * 64 * 3;

    scan_kernel<<<1, 1024>>>(seq);
    fill_kernel<<<(N_RES + 255) / 256, 256>>>(seq, atoms);

    int wgrid = (WATM_T_ELEMS + WAMN_T_ELEMS + 255) / 256;
    transpose_w_kernel<<<wgrid, 256>>>(W_amn, W_atm);

    diff_kernel<<<(BATCH * atoms + 255) / 256, 256>>>(pos_atm, pos_amn, atoms);

    int grid = (nrows + ROWS_PER_BLK - 1) / ROWS_PER_BLK;
    posmix_main<<<grid, 256>>>(out_atm, out_amn, atoms, nrows);
}